// round 1
// baseline (speedup 1.0000x reference)
#include <cuda_runtime.h>
#include <cuda_bf16.h>

#define GRID_BLOCKS 1184
#define MAX_BLOCKS  2048
#define THREADS     256

// Per-block partial sums (scratch; no device allocation allowed)
__device__ float g_partials[MAX_BLOCKS];

__device__ __forceinline__ float poly_elem(float x, float t) {
    // t is exactly 0.0 or 1.0. pt = sigmoid(t>0 ? x : -x), clipped.
    float xp = (t > 0.0f) ? x : -x;
    float pt = __fdividef(1.0f, 1.0f + __expf(-xp));
    pt = fminf(fmaxf(pt, 1.0e-4f), 1.0f - 1.0e-4f);
    // ce = -log(pt)  (log clamp at -100 can never fire after the clip)
    // poly = ce + 2*(1 - pt)
    return fmaf(-2.0f, pt, 2.0f) - __logf(pt);
}

__device__ __forceinline__ float block_reduce_sum(float val) {
    #pragma unroll
    for (int o = 16; o > 0; o >>= 1)
        val += __shfl_down_sync(0xffffffffu, val, o);
    __shared__ float sh[32];
    int lane = threadIdx.x & 31;
    int wid  = threadIdx.x >> 5;
    if (lane == 0) sh[wid] = val;
    __syncthreads();
    int nwarps = blockDim.x >> 5;
    val = (threadIdx.x < nwarps) ? sh[lane] : 0.0f;
    if (wid == 0) {
        #pragma unroll
        for (int o = 16; o > 0; o >>= 1)
            val += __shfl_down_sync(0xffffffffu, val, o);
    }
    return val;
}

__global__ void __launch_bounds__(THREADS)
hm_poly_partial_kernel(const float4* __restrict__ x4,
                       const float4* __restrict__ t4,
                       int n4) {
    float sum = 0.0f;
    int stride = gridDim.x * blockDim.x;
    for (int i = blockIdx.x * blockDim.x + threadIdx.x; i < n4; i += stride) {
        float4 xv = x4[i];
        float4 tv = t4[i];
        sum += poly_elem(xv.x, tv.x);
        sum += poly_elem(xv.y, tv.y);
        sum += poly_elem(xv.z, tv.z);
        sum += poly_elem(xv.w, tv.w);
    }
    float bs = block_reduce_sum(sum);
    if (threadIdx.x == 0) g_partials[blockIdx.x] = bs;
}

__global__ void __launch_bounds__(THREADS)
finalize_kernel(const float* __restrict__ cls_preds,
                const float* __restrict__ cls_gts,
                float* __restrict__ out,
                int nblocks, int n_hm, int B) {
    // --- hm partial reduce in double ---
    double s = 0.0;
    for (int i = threadIdx.x; i < nblocks; i += blockDim.x)
        s += (double)g_partials[i];
    #pragma unroll
    for (int o = 16; o > 0; o >>= 1)
        s += __shfl_down_sync(0xffffffffu, s, o);
    __shared__ double shd[32];
    int lane = threadIdx.x & 31;
    int wid  = threadIdx.x >> 5;
    if (lane == 0) shd[wid] = s;
    __syncthreads();
    int nwarps = blockDim.x >> 5;
    s = (threadIdx.x < nwarps) ? shd[lane] : 0.0;
    if (wid == 0) {
        #pragma unroll
        for (int o = 16; o > 0; o >>= 1)
            s += __shfl_down_sync(0xffffffffu, s, o);
    }

    // --- cls BCE (tiny: B elements) ---
    float c = 0.0f;
    for (int i = threadIdx.x; i < B; i += blockDim.x) {
        float p = cls_preds[i];
        float g = cls_gts[i];
        float logp   = fmaxf(logf(p), -100.0f);
        float log1mp = fmaxf(logf(1.0f - p), -100.0f);
        c += -(g * logp + (1.0f - g) * log1mp);
    }
    float cs = block_reduce_sum(c);

    if (threadIdx.x == 0) {
        // hm_loss = sum / (H*W) / B ; with C=1, H*W*B == n_hm
        out[0] = (float)(s / (double)n_hm);
        out[1] = (cs / (float)B) * 0.05f;
    }
}

extern "C" void kernel_launch(void* const* d_in, const int* in_sizes, int n_in,
                              void* d_out, int out_size) {
    const float* hm_outputs = (const float*)d_in[0];
    const float* hm_targets = (const float*)d_in[1];
    const float* cls_preds  = (const float*)d_in[2];
    const float* cls_gts    = (const float*)d_in[3];
    float* out = (float*)d_out;

    int n_hm = in_sizes[0];           // B*C*H*W = 9,437,184 (divisible by 4)
    int B    = in_sizes[2];           // 64
    int n4   = n_hm >> 2;

    hm_poly_partial_kernel<<<GRID_BLOCKS, THREADS>>>(
        (const float4*)hm_outputs, (const float4*)hm_targets, n4);
    finalize_kernel<<<1, THREADS>>>(cls_preds, cls_gts, out,
                                    GRID_BLOCKS, n_hm, B);
}

// round 4
// speedup vs baseline: 1.0019x; 1.0019x over previous
#include <cuda_runtime.h>
#include <cuda_bf16.h>

#define GRID_BLOCKS 1184
#define THREADS     256
#define SCALE       4194304.0   // 2^22 fixed-point scale for deterministic u64 accumulation

// Scratch accumulators (zero-initialized at module load; last block resets them
// after each use so the kernel is graph-replayable and deterministic).
__device__ unsigned long long g_sum;
__device__ unsigned int       g_count;

__device__ __forceinline__ float poly_elem(float x, float t) {
    // t is exactly 0.0 or 1.0. pt = sigmoid(t>0 ? x : -x), clipped symmetric.
    float xp = (t > 0.0f) ? x : -x;
    float pt = __fdividef(1.0f, 1.0f + __expf(-xp));
    pt = fminf(fmaxf(pt, 1.0e-4f), 1.0f - 1.0e-4f);
    // poly = -log(pt) + 2*(1 - pt); the -100 log clamp can never fire after the clip.
    return fmaf(-2.0f, pt, 2.0f) - __logf(pt);
}

__device__ __forceinline__ float block_reduce_sum(float val) {
    #pragma unroll
    for (int o = 16; o > 0; o >>= 1)
        val += __shfl_down_sync(0xffffffffu, val, o);
    __shared__ float sh[32];
    int lane = threadIdx.x & 31;
    int wid  = threadIdx.x >> 5;
    if (lane == 0) sh[wid] = val;
    __syncthreads();
    int nwarps = blockDim.x >> 5;
    val = (threadIdx.x < nwarps) ? sh[lane] : 0.0f;
    if (wid == 0) {
        #pragma unroll
        for (int o = 16; o > 0; o >>= 1)
            val += __shfl_down_sync(0xffffffffu, val, o);
    }
    return val;
}

__global__ void __launch_bounds__(THREADS)
poly_loss_fused_kernel(const float4* __restrict__ x4,
                       const float4* __restrict__ t4,
                       const float*  __restrict__ cls_preds,
                       const float*  __restrict__ cls_gts,
                       float*        __restrict__ out,
                       int n4, int n_hm, int B) {
    // ---- main heatmap reduction ----
    float sum = 0.0f;
    int stride = gridDim.x * blockDim.x;
    for (int i = blockIdx.x * blockDim.x + threadIdx.x; i < n4; i += stride) {
        float4 xv = x4[i];
        float4 tv = t4[i];
        sum += poly_elem(xv.x, tv.x);
        sum += poly_elem(xv.y, tv.y);
        sum += poly_elem(xv.z, tv.z);
        sum += poly_elem(xv.w, tv.w);
    }
    float bs = block_reduce_sum(sum);

    __shared__ bool is_last;
    if (threadIdx.x == 0) {
        // poly_elem > 0 always, so bs >= 0; two's-complement cast is safe regardless.
        long long q = llrint((double)bs * SCALE);
        atomicAdd(&g_sum, (unsigned long long)q);
        __threadfence();
        unsigned int prev = atomicAdd(&g_count, 1u);
        is_last = (prev == gridDim.x - 1u);
    }
    __syncthreads();

    // ---- last block finalizes ----
    if (is_last) {
        // cls BCE over B=64 elements (deterministic fixed-tree reduce)
        float c = 0.0f;
        for (int i = threadIdx.x; i < B; i += blockDim.x) {
            float p = cls_preds[i];
            float g = cls_gts[i];
            float logp   = fmaxf(logf(p), -100.0f);
            float log1mp = fmaxf(logf(1.0f - p), -100.0f);
            c += -(g * logp + (1.0f - g) * log1mp);
        }
        __syncthreads();             // protect shared mem reuse in block_reduce
        float cs = block_reduce_sum(c);

        if (threadIdx.x == 0) {
            __threadfence();         // make all blocks' g_sum updates visible
            long long total_q = (long long)g_sum;
            double total = (double)total_q / SCALE;
            out[0] = (float)(total / (double)n_hm);   // sum/(H*W)/B with C=1
            out[1] = (cs / (float)B) * 0.05f;
            // reset scratch for the next graph replay
            g_sum   = 0ull;
            g_count = 0u;
        }
    }
}

extern "C" void kernel_launch(void* const* d_in, const int* in_sizes, int n_in,
                              void* d_out, int out_size) {
    const float* hm_outputs = (const float*)d_in[0];
    const float* hm_targets = (const float*)d_in[1];
    const float* cls_preds  = (const float*)d_in[2];
    const float* cls_gts    = (const float*)d_in[3];
    float* out = (float*)d_out;

    int n_hm = in_sizes[0];           // B*C*H*W = 9,437,184 (divisible by 4)
    int B    = in_sizes[2];           // 64
    int n4   = n_hm >> 2;

    poly_loss_fused_kernel<<<GRID_BLOCKS, THREADS>>>(
        (const float4*)hm_outputs, (const float4*)hm_targets,
        cls_preds, cls_gts, out, n4, n_hm, B);
}